// round 6
// baseline (speedup 1.0000x reference)
#include <cuda_runtime.h>
#include <cstdint>

#define N_  2
#define T_  2048
#define D_  512
#define H_  8
#define HD_ 64
#define NTD (N_*T_*D_)

// softmaxed per-head scale: [stream][h*64+hd]
__device__ float g_sc[2][H_*HD_];
// fragment-layout operand arrays (tf32 bit patterns)
// Q A-frags: [sb(32)][t16(128)][ks(8)][word(128)]
__device__ uint32_t g_qf[32u*128u*8u*128u];
// K B-frags (QK mma): [sb(32)][kt(32)][f(64)=j*8+ks][word(64)]
__device__ uint32_t g_kf[32u*32u*64u*64u];
// V B-frags (AV mma): [sb(32)][kt(32)][f(64)=dg*8+j][word(64)]
__device__ uint32_t g_vf[32u*32u*64u*64u];
// p scratch: [blk(512)][warp(8)][kt(32)][j(8)*lane(32)] float4 (A-frag layout)
__device__ float4 g_p[512u*8u*32u*256u];

// ---------------------------------------------------------------------------
__global__ void scale_kernel(const float* __restrict__ isc,
                             const float* __restrict__ lsc) {
    int i = threadIdx.x;
    if (i >= 16) return;
    int s = i >> 3, h = i & 7;
    const float* src = (s == 0 ? isc : lsc) + h * HD_;
    float m = -1e30f;
    for (int d = 0; d < HD_; d++) m = fmaxf(m, src[d]);
    float Z = 0.f;
    for (int d = 0; d < HD_; d++) Z += __expf(src[d] - m);
    float inv = 1.f / Z;
    for (int d = 0; d < HD_; d++) g_sc[s][h*HD_ + d] = __expf(src[d] - m) * inv;
}

__device__ __forceinline__ uint32_t f2tf(float x) {
    uint32_t r;
    asm("cvt.rna.tf32.f32 %0, %1;" : "=r"(r) : "f"(x));
    return r;
}

__device__ __forceinline__ void mma_tf32(float (&d)[4],
                                         uint32_t a0, uint32_t a1, uint32_t a2, uint32_t a3,
                                         uint32_t b0, uint32_t b1) {
    asm volatile(
        "mma.sync.aligned.m16n8k8.row.col.f32.tf32.tf32.f32 "
        "{%0,%1,%2,%3}, {%4,%5,%6,%7}, {%8,%9}, {%0,%1,%2,%3};"
        : "+f"(d[0]), "+f"(d[1]), "+f"(d[2]), "+f"(d[3])
        : "r"(a0), "r"(a1), "r"(a2), "r"(a3), "r"(b0), "r"(b1));
}

// store one projected value (row t of (n,h), channel hd) into its frag slot
__device__ __forceinline__ void store_frag(int three, int sb, int t, int hd, float v) {
    uint32_t b = f2tf(v);
    if (three == 0) {          // Q: A-frag layout
        int idx = ((sb * 128 + (t >> 4)) * 8 + (hd >> 3)) * 128
                + (t & 7) * 16 + ((hd >> 2) & 1) * 2 + ((t >> 3) & 1) + (hd & 3) * 4;
        g_qf[idx] = b;
    } else if (three == 1) {   // K: B-frag (QK) layout
        int kt = (t >> 6) & 31;
        int f = ((t >> 3) & 7) * 8 + (hd >> 3);
        int word = (t & 7) * 8 + ((hd >> 2) & 1) + (hd & 3) * 2;
        g_kf[((sb * 32 + kt) * 64 + f) * 64 + word] = b;
    } else {                   // V: B-frag (AV) layout
        int kt = (t >> 6) & 31;
        int f = (hd >> 3) * 8 + ((t >> 3) & 7);
        int word = ((hd >> 2) & 1) * 32 + (t & 3) * 2 + ((t >> 2) & 1) + (hd & 3) * 8;
        g_vf[((sb * 32 + kt) * 64 + f) * 64 + word] = b;
    }
}

// ---------------------------------------------------------------------------
// QKV projection, tf32 mma, 128(M) x 64(N) tiles, K=512, reg-prefetched.
// Writes directly into fragment-layout arrays.
// ---------------------------------------------------------------------------
__global__ __launch_bounds__(256, 2)
void qkv_tf32_kernel(const float* __restrict__ z, const float* __restrict__ W, int stream) {
    __shared__ uint32_t ap[4224];   // A-frags: 8 rowblocks * 4 ks * 132
    __shared__ uint32_t bp[2112];   // B-frags: 8 colblocks * 4 ks * 66
    int tid = threadIdx.x;
    int w = tid >> 5, lane = tid & 31;
    int g = lane >> 2, c = lane & 3;
    int rq = w & 3, nh = w >> 2;
    int c0 = blockIdx.x * 64;
    int m0 = blockIdx.y * 128;

    float acc[2][4][4];
    #pragma unroll
    for (int a = 0; a < 2; a++)
        #pragma unroll
        for (int b = 0; b < 4; b++)
            #pragma unroll
            for (int e = 0; e < 4; e++) acc[a][b][e] = 0.f;

    float4 zr[4], wr[2];
    #pragma unroll
    for (int p = 0; p < 4; p++) {
        int i4 = tid + p * 256;
        zr[p] = *(const float4*)&z[(m0 + (i4 >> 3)) * 512 + (i4 & 7) * 4];
    }
    #pragma unroll
    for (int p = 0; p < 2; p++) {
        int i4 = tid + p * 256;
        wr[p] = *(const float4*)&W[(c0 + (i4 >> 3)) * 512 + (i4 & 7) * 4];
    }

    for (int it = 0; it < 16; it++) {
        __syncthreads();
        #pragma unroll
        for (int p = 0; p < 4; p++) {
            int i4 = tid + p * 256;
            int row = i4 >> 3, kq = i4 & 7;
            int base = ((row >> 4) * 4 + (kq >> 1)) * 132 + (row & 7) * 16
                     + (kq & 1) * 2 + ((row >> 3) & 1);
            ap[base + 0]  = f2tf(zr[p].x);
            ap[base + 4]  = f2tf(zr[p].y);
            ap[base + 8]  = f2tf(zr[p].z);
            ap[base + 12] = f2tf(zr[p].w);
        }
        #pragma unroll
        for (int p = 0; p < 2; p++) {
            int i4 = tid + p * 256;
            int col = i4 >> 3, kq = i4 & 7;
            int base = ((col >> 3) * 4 + (kq >> 1)) * 66 + (col & 7) * 8 + (kq & 1);
            bp[base + 0] = f2tf(wr[p].x);
            bp[base + 2] = f2tf(wr[p].y);
            bp[base + 4] = f2tf(wr[p].z);
            bp[base + 6] = f2tf(wr[p].w);
        }
        __syncthreads();
        if (it < 15) {
            int k0 = (it + 1) * 32;
            #pragma unroll
            for (int p = 0; p < 4; p++) {
                int i4 = tid + p * 256;
                zr[p] = *(const float4*)&z[(m0 + (i4 >> 3)) * 512 + k0 + (i4 & 7) * 4];
            }
            #pragma unroll
            for (int p = 0; p < 2; p++) {
                int i4 = tid + p * 256;
                wr[p] = *(const float4*)&W[(c0 + (i4 >> 3)) * 512 + k0 + (i4 & 7) * 4];
            }
        }
        #pragma unroll
        for (int ks = 0; ks < 4; ks++) {
            uint4 a0 = *(const uint4*)&ap[((rq * 2 + 0) * 4 + ks) * 132 + lane * 4];
            uint4 a1 = *(const uint4*)&ap[((rq * 2 + 1) * 4 + ks) * 132 + lane * 4];
            #pragma unroll
            for (int np = 0; np < 4; np++) {
                uint2 b = *(const uint2*)&bp[((nh * 4 + np) * 4 + ks) * 66 + lane * 2];
                mma_tf32(acc[0][np], a0.x, a0.y, a0.z, a0.w, b.x, b.y);
                mma_tf32(acc[1][np], a1.x, a1.y, a1.z, a1.w, b.x, b.y);
            }
        }
    }

    int three = c0 >> 9;
    int h = (c0 >> 6) & 7;
    #pragma unroll
    for (int grp = 0; grp < 2; grp++) {
        #pragma unroll
        for (int np = 0; np < 4; np++) {
            int colb = nh * 32 + np * 8 + 2 * c;
            float sx = 1.f, sy = 1.f;
            if (three == 0) {
                float2 s2 = *(const float2*)&g_sc[stream][h * 64 + colb];
                sx = s2.x; sy = s2.y;
            }
            int m = m0 + rq * 32 + grp * 16 + g;
            int n = m >> 11, t = m & 2047;
            int sb = (stream * 2 + n) * 8 + h;
            store_frag(three, sb, t,     colb,     acc[grp][np][0] * sx);
            store_frag(three, sb, t,     colb + 1, acc[grp][np][1] * sy);
            store_frag(three, sb, t + 8, colb,     acc[grp][np][2] * sx);
            store_frag(three, sb, t + 8, colb + 1, acc[grp][np][3] * sy);
        }
    }
}

// ---------------------------------------------------------------------------
// Dual attention, tf32 mma, two-pass via p-scratch, smem-free mainloops.
// Block = (stream s, batch n, head h, 128-row q-tile). 8 warps.
// Pass 1 (16 rows/warp): Q frags in regs, K frags via LDG; online (m,Z);
//   p=exp(S-m_run) -> gmem A-frags.
// Pass 2 (32 rows x 32 dcols/warp): attn = p*corr, anti_w = exp(-attn);
//   Vc/Vf B-frags via LDG.
// anti = softmax(max(attn)-attn) == softmax(-attn)
// ---------------------------------------------------------------------------
__global__ __launch_bounds__(256, 2)
void attn_kernel(const float* __restrict__ sp, float* __restrict__ out) {
    __shared__ float mr[8][512];
    __shared__ float cr[8][512];
    __shared__ float swt[128];
    int tid = threadIdx.x;
    int w = tid >> 5, lane = tid & 31;
    int g = lane >> 2, c = lane & 3;
    int qt = blockIdx.x, h = blockIdx.y, zb = blockIdx.z;
    int s = zb >> 1, n = zb & 1;
    int blk = (zb * 8 + h) * 16 + qt;

    int sbq  = (s * 2 + n) * 8 + h;
    int sbk  = ((1 - s) * 2 + n) * 8 + h;
    int sbvc = ((1 - s) * 2 + n) * 8 + h;
    int sbvf = (s * 2 + n) * 8 + h;
    float* ob = out + s * NTD;
    float spv = *sp;

    // Q A-frags for this warp's 16 rows: resident in registers for both passes
    const uint4* qfp = (const uint4*)g_qf + ((sbq * 128 + qt * 8 + w) * 8) * 32 + lane;
    uint4 qf[8];
    #pragma unroll
    for (int ks = 0; ks < 8; ks++) qf[ks] = qfp[ks * 32];

    float m0 = -1e30f, m1 = -1e30f, Z0 = 0.f, Z1 = 0.f;
    const uint2* kfb = (const uint2*)g_kf + (sbk * 32) * 2048 + lane;

    // ======================= pass 1: QK^T + stats + p =======================
    for (int kt = 0; kt < 32; kt++) {
        const uint2* kf = kfb + kt * 2048;
        float S[8][4];
        #pragma unroll
        for (int j = 0; j < 8; j++) { S[j][0]=0.f; S[j][1]=0.f; S[j][2]=0.f; S[j][3]=0.f; }
        #pragma unroll
        for (int ks = 0; ks < 8; ks++) {
            uint4 a = qf[ks];
            #pragma unroll
            for (int j = 0; j < 8; j++) {
                uint2 b = kf[(j * 8 + ks) * 32];
                mma_tf32(S[j], a.x, a.y, a.z, a.w, b.x, b.y);
            }
        }
        // online stats: rows g (S[j][0..1]) and g+8 (S[j][2..3]), quad-private
        float t0 = -1e30f, t1 = -1e30f;
        #pragma unroll
        for (int j = 0; j < 8; j++) {
            t0 = fmaxf(t0, fmaxf(S[j][0], S[j][1]));
            t1 = fmaxf(t1, fmaxf(S[j][2], S[j][3]));
        }
        t0 = fmaxf(t0, __shfl_xor_sync(~0u, t0, 1));
        t0 = fmaxf(t0, __shfl_xor_sync(~0u, t0, 2));
        t1 = fmaxf(t1, __shfl_xor_sync(~0u, t1, 1));
        t1 = fmaxf(t1, __shfl_xor_sync(~0u, t1, 2));
        float mn0 = fmaxf(m0, t0), mn1 = fmaxf(m1, t1);

        float P[8][4];
        float ps0 = 0.f, ps1 = 0.f;
        #pragma unroll
        for (int j = 0; j < 8; j++) {
            P[j][0] = __expf(S[j][0] - mn0);
            P[j][1] = __expf(S[j][1] - mn0);
            P[j][2] = __expf(S[j][2] - mn1);
            P[j][3] = __expf(S[j][3] - mn1);
            ps0 += P[j][0] + P[j][1];
            ps1 += P[j][2] + P[j][3];
        }
        ps0 += __shfl_xor_sync(~0u, ps0, 1);
        ps0 += __shfl_xor_sync(~0u, ps0, 2);
        ps1 += __shfl_xor_sync(~0u, ps1, 1);
        ps1 += __shfl_xor_sync(~0u, ps1, 2);
        Z0 = Z0 * __expf(m0 - mn0) + ps0; m0 = mn0;
        Z1 = Z1 * __expf(m1 - mn1) + ps1; m1 = mn1;
        if (c == 0) {
            mr[w][kt * 16 + g]     = mn0;
            mr[w][kt * 16 + g + 8] = mn1;
        }
        // shuffle C-frag -> A-frag layout; coalesced store of p
        int src1 = (lane & ~3) | (c >> 1);
        int src2 = src1 + 2;
        bool odd = (lane & 1);
        float4* pg = &g_p[((blk * 8 + w) * 32 + kt) * 256 + lane];
        #pragma unroll
        for (int j = 0; j < 8; j++) {
            float x0 = __shfl_sync(~0u, P[j][0], src1);
            float x1 = __shfl_sync(~0u, P[j][1], src1);
            float y0 = __shfl_sync(~0u, P[j][2], src1);
            float y1 = __shfl_sync(~0u, P[j][3], src1);
            float u0 = __shfl_sync(~0u, P[j][0], src2);
            float u1 = __shfl_sync(~0u, P[j][1], src2);
            float v0 = __shfl_sync(~0u, P[j][2], src2);
            float v1 = __shfl_sync(~0u, P[j][3], src2);
            float4 o;
            o.x = odd ? x1 : x0;
            o.y = odd ? y1 : y0;
            o.z = odd ? u1 : u0;
            o.w = odd ? v1 : v0;
            pg[j * 32] = o;
        }
    }

    // =================== corr table: exp(m_run - m_fin)/Z ===================
    float iZ0 = 1.f / Z0, iZ1 = 1.f / Z1;
    __syncthreads();
    #pragma unroll
    for (int i = 0; i < 16; i++) {
        int idx = lane + i * 32;
        int r = idx & 15;
        int srcl = (r & 7) * 4;
        float mfa = __shfl_sync(~0u, m0, srcl);
        float mfb = __shfl_sync(~0u, m1, srcl);
        float iza = __shfl_sync(~0u, iZ0, srcl);
        float izb = __shfl_sync(~0u, iZ1, srcl);
        float mf = (r < 8) ? mfa : mfb;
        float iz = (r < 8) ? iza : izb;
        cr[w][idx] = __expf(mr[w][idx] - mf) * iz;
    }
    __syncthreads();

    // ======================= pass 2: attn/anti AV ===========================
    int rq = w & 3, dh = w >> 2;
    float accA[2][4][4], accW[2][4][4];
    #pragma unroll
    for (int grp = 0; grp < 2; grp++)
        #pragma unroll
        for (int dp = 0; dp < 4; dp++)
            #pragma unroll
            for (int e = 0; e < 4; e++) { accA[grp][dp][e] = 0.f; accW[grp][dp][e] = 0.f; }
    float sw0[2] = {0.f, 0.f}, sw1[2] = {0.f, 0.f};

    const uint2* vcb = (const uint2*)g_vf + (sbvc * 32) * 2048 + lane;
    const uint2* vfb = (const uint2*)g_vf + (sbvf * 32) * 2048 + lane;
    int pw0 = rq * 2, pw1 = rq * 2 + 1;

    for (int kt = 0; kt < 32; kt++) {
        const uint2* vcp = vcb + kt * 2048;
        const uint2* vfp = vfb + kt * 2048;
        float cr00 = cr[pw0][kt * 16 + g];
        float cr01 = cr[pw0][kt * 16 + g + 8];
        float cr10 = cr[pw1][kt * 16 + g];
        float cr11 = cr[pw1][kt * 16 + g + 8];
        const float4* pg0 = &g_p[((blk * 8 + pw0) * 32 + kt) * 256 + lane];
        const float4* pg1 = &g_p[((blk * 8 + pw1) * 32 + kt) * 256 + lane];
        #pragma unroll
        for (int j = 0; j < 8; j++) {
            float4 p0 = pg0[j * 32];
            float4 p1 = pg1[j * 32];
            float a00 = p0.x * cr00, a01 = p0.y * cr01, a02 = p0.z * cr00, a03 = p0.w * cr01;
            float a10 = p1.x * cr10, a11 = p1.y * cr11, a12 = p1.z * cr10, a13 = p1.w * cr11;
            float w00 = __expf(-a00), w01 = __expf(-a01), w02 = __expf(-a02), w03 = __expf(-a03);
            float w10 = __expf(-a10), w11 = __expf(-a11), w12 = __expf(-a12), w13 = __expf(-a13);
            sw0[0] += w00 + w02; sw1[0] += w01 + w03;
            sw0[1] += w10 + w12; sw1[1] += w11 + w13;
            uint32_t A00=f2tf(a00), A01=f2tf(a01), A02=f2tf(a02), A03=f2tf(a03);
            uint32_t A10=f2tf(a10), A11=f2tf(a11), A12=f2tf(a12), A13=f2tf(a13);
            uint32_t W00=f2tf(w00), W01=f2tf(w01), W02=f2tf(w02), W03=f2tf(w03);
            uint32_t W10=f2tf(w10), W11=f2tf(w11), W12=f2tf(w12), W13=f2tf(w13);
            #pragma unroll
            for (int dp = 0; dp < 4; dp++) {
                int dg = dh * 4 + dp;
                uint2 bc = vcp[(dg * 8 + j) * 32];
                uint2 bf = vfp[(dg * 8 + j) * 32];
                mma_tf32(accA[0][dp], A00, A01, A02, A03, bc.x, bc.y);
                mma_tf32(accA[1][dp], A10, A11, A12, A13, bc.x, bc.y);
                mma_tf32(accW[0][dp], W00, W01, W02, W03, bf.x, bf.y);
                mma_tf32(accW[1][dp], W10, W11, W12, W13, bf.x, bf.y);
            }
        }
    }

    // anti row sums: quad-reduce, publish from dh==0 warps, broadcast
    #pragma unroll
    for (int grp = 0; grp < 2; grp++) {
        sw0[grp] += __shfl_xor_sync(~0u, sw0[grp], 1);
        sw0[grp] += __shfl_xor_sync(~0u, sw0[grp], 2);
        sw1[grp] += __shfl_xor_sync(~0u, sw1[grp], 1);
        sw1[grp] += __shfl_xor_sync(~0u, sw1[grp], 2);
    }
    __syncthreads();
    if (dh == 0 && c == 0) {
        #pragma unroll
        for (int grp = 0; grp < 2; grp++) {
            swt[rq * 32 + grp * 16 + g]     = sw0[grp];
            swt[rq * 32 + grp * 16 + g + 8] = sw1[grp];
        }
    }
    __syncthreads();

    #pragma unroll
    for (int grp = 0; grp < 2; grp++) {
        int r = rq * 32 + grp * 16 + g;
        float iw0 = (1.f - spv) / swt[r];
        float iw1 = (1.f - spv) / swt[r + 8];
        int t0r = qt * 128 + r;
        #pragma unroll
        for (int dp = 0; dp < 4; dp++) {
            int col = h * 64 + dh * 32 + dp * 8 + 2 * c;
            *(float2*)&ob[(n * T_ + t0r) * D_ + col] =
                make_float2(spv * accA[grp][dp][0] + iw0 * accW[grp][dp][0],
                            spv * accA[grp][dp][1] + iw0 * accW[grp][dp][1]);
            *(float2*)&ob[(n * T_ + t0r + 8) * D_ + col] =
                make_float2(spv * accA[grp][dp][2] + iw1 * accW[grp][dp][2],
                            spv * accA[grp][dp][3] + iw1 * accW[grp][dp][3]);
        }
    }
}

// ---------------------------------------------------------------------------
extern "C" void kernel_launch(void* const* d_in, const int* in_sizes, int n_in,
                              void* d_out, int out_size) {
    const float* x   = (const float*)d_in[0];
    const float* y   = (const float*)d_in[1];
    const float* iw  = (const float*)d_in[2];
    const float* lw  = (const float*)d_in[3];
    const float* isc = (const float*)d_in[4];
    const float* lsc = (const float*)d_in[5];
    const float* sp  = (const float*)d_in[6];
    float* out = (float*)d_out;

    scale_kernel<<<1, 32>>>(isc, lsc);

    dim3 gq(1536 / 64, 4096 / 128);
    qkv_tf32_kernel<<<gq, 256>>>(x, iw, 0);
    qkv_tf32_kernel<<<gq, 256>>>(y, lw, 1);

    dim3 g2(T_ / 128, H_, 4);
    attn_kernel<<<g2, 256>>>(sp, out);
}

// round 9
// speedup vs baseline: 1.1623x; 1.1623x over previous
#include <cuda_runtime.h>
#include <cstdint>

#define N_  2
#define T_  2048
#define D_  512
#define H_  8
#define HD_ 64
#define NTD (N_*T_*D_)
#define NHTHD (N_*H_*T_*HD_)

// Scratch: [stream][q/k/v][n,h,t,hd], values pre-rounded to tf32 (rna)
__device__ float g_buf[2][3][NHTHD];
__device__ float g_sc[2][H_*HD_];

// attn smem word offsets
#define QP 0                    // Q A-frags: 64 groups * 132 = 8448 words
#define TB 8448                 // tile double-buffer: 2 * 6144 words
                                // per buf: K @+0 (2048), Vc @+2048, Vf @+4096
#define SMEM_WORDS (8448 + 2*6144)   // 20736 words = 82944 B

// ---------------------------------------------------------------------------
__global__ void scale_kernel(const float* __restrict__ isc,
                             const float* __restrict__ lsc) {
    int i = threadIdx.x;
    if (i >= 16) return;
    int s = i >> 3, h = i & 7;
    const float* src = (s == 0 ? isc : lsc) + h * HD_;
    float m = -1e30f;
    for (int d = 0; d < HD_; d++) m = fmaxf(m, src[d]);
    float Z = 0.f;
    for (int d = 0; d < HD_; d++) Z += __expf(src[d] - m);
    float inv = 1.f / Z;
    for (int d = 0; d < HD_; d++) g_sc[s][h*HD_ + d] = __expf(src[d] - m) * inv;
}

__device__ __forceinline__ uint32_t f2tf(float x) {
    uint32_t r;
    asm("cvt.rna.tf32.f32 %0, %1;" : "=r"(r) : "f"(x));
    return r;
}
__device__ __forceinline__ float tf32r(float x) { return __uint_as_float(f2tf(x)); }

__device__ __forceinline__ void mma_tf32(float (&d)[4],
                                         uint32_t a0, uint32_t a1, uint32_t a2, uint32_t a3,
                                         uint32_t b0, uint32_t b1) {
    asm volatile(
        "mma.sync.aligned.m16n8k8.row.col.f32.tf32.tf32.f32 "
        "{%0,%1,%2,%3}, {%4,%5,%6,%7}, {%8,%9}, {%0,%1,%2,%3};"
        : "+f"(d[0]), "+f"(d[1]), "+f"(d[2]), "+f"(d[3])
        : "r"(a0), "r"(a1), "r"(a2), "r"(a3), "r"(b0), "r"(b1));
}

// ---------------------------------------------------------------------------
// QKV projection, tf32 mma, 128(M) x 64(N) tiles, K=512, reg-prefetched.
// Writes tf32-rounded fp32 to plain [n,h,t,hd] layout. (Unchanged from R6.)
// ---------------------------------------------------------------------------
__global__ __launch_bounds__(256, 2)
void qkv_tf32_kernel(const float* __restrict__ z, const float* __restrict__ W, int stream) {
    __shared__ uint32_t ap[4224];
    __shared__ uint32_t bp[2112];
    int tid = threadIdx.x;
    int w = tid >> 5, lane = tid & 31;
    int g = lane >> 2, c = lane & 3;
    int rq = w & 3, nh = w >> 2;
    int c0 = blockIdx.x * 64;
    int m0 = blockIdx.y * 128;

    float acc[2][4][4];
    #pragma unroll
    for (int a = 0; a < 2; a++)
        #pragma unroll
        for (int b = 0; b < 4; b++)
            #pragma unroll
            for (int e = 0; e < 4; e++) acc[a][b][e] = 0.f;

    float4 zr[4], wr[2];
    #pragma unroll
    for (int p = 0; p < 4; p++) {
        int i4 = tid + p * 256;
        zr[p] = *(const float4*)&z[(m0 + (i4 >> 3)) * 512 + (i4 & 7) * 4];
    }
    #pragma unroll
    for (int p = 0; p < 2; p++) {
        int i4 = tid + p * 256;
        wr[p] = *(const float4*)&W[(c0 + (i4 >> 3)) * 512 + (i4 & 7) * 4];
    }

    for (int it = 0; it < 16; it++) {
        __syncthreads();
        #pragma unroll
        for (int p = 0; p < 4; p++) {
            int i4 = tid + p * 256;
            int row = i4 >> 3, kq = i4 & 7;
            int base = ((row >> 4) * 4 + (kq >> 1)) * 132 + (row & 7) * 16
                     + (kq & 1) * 2 + ((row >> 3) & 1);
            ap[base + 0]  = f2tf(zr[p].x);
            ap[base + 4]  = f2tf(zr[p].y);
            ap[base + 8]  = f2tf(zr[p].z);
            ap[base + 12] = f2tf(zr[p].w);
        }
        #pragma unroll
        for (int p = 0; p < 2; p++) {
            int i4 = tid + p * 256;
            int col = i4 >> 3, kq = i4 & 7;
            int base = ((col >> 3) * 4 + (kq >> 1)) * 66 + (col & 7) * 8 + (kq & 1);
            bp[base + 0] = f2tf(wr[p].x);
            bp[base + 2] = f2tf(wr[p].y);
            bp[base + 4] = f2tf(wr[p].z);
            bp[base + 6] = f2tf(wr[p].w);
        }
        __syncthreads();
        if (it < 15) {
            int k0 = (it + 1) * 32;
            #pragma unroll
            for (int p = 0; p < 4; p++) {
                int i4 = tid + p * 256;
                zr[p] = *(const float4*)&z[(m0 + (i4 >> 3)) * 512 + k0 + (i4 & 7) * 4];
            }
            #pragma unroll
            for (int p = 0; p < 2; p++) {
                int i4 = tid + p * 256;
                wr[p] = *(const float4*)&W[(c0 + (i4 >> 3)) * 512 + k0 + (i4 & 7) * 4];
            }
        }
        #pragma unroll
        for (int ks = 0; ks < 4; ks++) {
            uint4 a0 = *(const uint4*)&ap[((rq * 2 + 0) * 4 + ks) * 132 + lane * 4];
            uint4 a1 = *(const uint4*)&ap[((rq * 2 + 1) * 4 + ks) * 132 + lane * 4];
            #pragma unroll
            for (int np = 0; np < 4; np++) {
                uint2 b = *(const uint2*)&bp[((nh * 4 + np) * 4 + ks) * 66 + lane * 2];
                mma_tf32(acc[0][np], a0.x, a0.y, a0.z, a0.w, b.x, b.y);
                mma_tf32(acc[1][np], a1.x, a1.y, a1.z, a1.w, b.x, b.y);
            }
        }
    }

    int three = c0 >> 9;
    int h = (c0 >> 6) & 7;
    float* dst = g_buf[stream][three];
    #pragma unroll
    for (int grp = 0; grp < 2; grp++) {
        #pragma unroll
        for (int np = 0; np < 4; np++) {
            int colb = nh * 32 + np * 8 + 2 * c;
            float sx = 1.f, sy = 1.f;
            if (three == 0) {
                float2 s2 = *(const float2*)&g_sc[stream][h * 64 + colb];
                sx = s2.x; sy = s2.y;
            }
            int m = m0 + rq * 32 + grp * 16 + g;
            int nn = m >> 11, t = m & 2047;
            *(float2*)&dst[((nn * 8 + h) * 2048 + t) * 64 + colb] =
                make_float2(tf32r(acc[grp][np][0] * sx), tf32r(acc[grp][np][1] * sy));
            int m2 = m + 8;
            int nn2 = m2 >> 11, t2 = m2 & 2047;
            *(float2*)&dst[((nn2 * 8 + h) * 2048 + t2) * 64 + colb] =
                make_float2(tf32r(acc[grp][np][2] * sx), tf32r(acc[grp][np][3] * sy));
        }
    }
}

// ---------------------------------------------------------------------------
// Dual attention. Block = (stream, n, h, 128-row q-tile), 8 warps x 16 rows.
// No-max softmax (|S| <= ~1): pass1 computes Z only; pass2 recomputes S.
// K/V tiles double-buffered via LDG->register->STS in XOR-swizzled layout.
// anti = softmax(max(attn)-attn) == softmax(-attn)
// ---------------------------------------------------------------------------
__global__ __launch_bounds__(256, 2)
void attn_kernel(const float* __restrict__ sp, float* __restrict__ out) {
    extern __shared__ uint32_t smu[];
    int tid = threadIdx.x;
    int w = tid >> 5, lane = tid & 31;
    int g = lane >> 2, c = lane & 3;
    int qt = blockIdx.x, h = blockIdx.y, zb = blockIdx.z;
    int s = zb >> 1, n = zb & 1;

    const float* Qb  = g_buf[s][0]     + ((n * H_ + h) * T_ + qt * 128) * HD_;
    const float* Kb  = g_buf[1 - s][1] + ((n * H_ + h) * T_) * HD_;
    const float* Vcb = g_buf[1 - s][2] + ((n * H_ + h) * T_) * HD_;
    const float* Vfb = g_buf[s][2]     + ((n * H_ + h) * T_) * HD_;
    float* ob = out + s * NTD;
    float spv = *sp;

    // staging index for this thread (covers 512 float4 per pass over p-slots)
    // i4 = tid + p*256: key = i4>>4 (0..31), blk = i4&15 (16B chunk)
    // swizzled word: key*64 + ((blk ^ (key&7))<<2)  [+0..3]

    // stage Q [128x64] into A-frag layout once (values pre-rounded)
    #pragma unroll
    for (int p = 0; p < 8; p++) {
        int i4 = tid + p * 256;
        int row = i4 >> 4, kq = i4 & 15;
        float4 qv = *(const float4*)&Qb[row * 64 + kq * 4];
        int base = QP + ((row >> 4) * 8 + (kq >> 1)) * 132 + (row & 7) * 16
                 + (kq & 1) * 2 + ((row >> 3) & 1);
        smu[base + 0]  = __float_as_uint(qv.x);
        smu[base + 4]  = __float_as_uint(qv.y);
        smu[base + 8]  = __float_as_uint(qv.z);
        smu[base + 12] = __float_as_uint(qv.w);
    }

    // ======================= pass 1: Z = sum exp(S) =========================
    float4 kreg[2];
    #pragma unroll
    for (int p = 0; p < 2; p++) {
        int i4 = tid + p * 256;
        kreg[p] = *(const float4*)&Kb[(i4 >> 4) * 64 + (i4 & 15) * 4];
    }

    float zs0 = 0.f, zs1 = 0.f;
    for (int t = 0; t < 64; t++) {
        uint32_t kb = TB + (t & 1) * 6144;
        #pragma unroll
        for (int p = 0; p < 2; p++) {
            int i4 = tid + p * 256;
            int key = i4 >> 4, blk = i4 & 15;
            *(float4*)&smu[kb + key * 64 + ((blk ^ (key & 7)) << 2)] = kreg[p];
        }
        __syncthreads();
        if (t < 63) {
            #pragma unroll
            for (int p = 0; p < 2; p++) {
                int i4 = tid + p * 256;
                kreg[p] = *(const float4*)&Kb[(t + 1) * 2048 + (i4 >> 4) * 64 + (i4 & 15) * 4];
            }
        }
        float S[4][4];
        #pragma unroll
        for (int j = 0; j < 4; j++) { S[j][0]=0.f; S[j][1]=0.f; S[j][2]=0.f; S[j][3]=0.f; }
        #pragma unroll
        for (int ks = 0; ks < 8; ks++) {
            uint4 a = *(const uint4*)&smu[QP + (w * 8 + ks) * 132 + lane * 4];
            #pragma unroll
            for (int j = 0; j < 4; j++) {
                uint32_t base = kb + (j * 8 + g) * 64 + c;
                uint32_t b0 = smu[base + (((ks * 2) ^ g) << 2)];
                uint32_t b1 = smu[base + (((ks * 2 + 1) ^ g) << 2)];
                mma_tf32(S[j], a.x, a.y, a.z, a.w, b0, b1);
            }
        }
        #pragma unroll
        for (int j = 0; j < 4; j++) {
            zs0 += __expf(S[j][0]) + __expf(S[j][1]);
            zs1 += __expf(S[j][2]) + __expf(S[j][3]);
        }
    }
    zs0 += __shfl_xor_sync(~0u, zs0, 1);
    zs0 += __shfl_xor_sync(~0u, zs0, 2);
    zs1 += __shfl_xor_sync(~0u, zs1, 1);
    zs1 += __shfl_xor_sync(~0u, zs1, 2);
    float iZ0 = 1.f / zs0, iZ1 = 1.f / zs1;
    __syncthreads();   // pass-1 buffers done before pass-2 restaging

    // ======================= pass 2: attn/anti AV ===========================
    float4 vreg[6];
    #pragma unroll
    for (int p = 0; p < 6; p++) {
        const float* src = (p < 2) ? Kb : (p < 4) ? Vcb : Vfb;
        int i4 = tid + (p & 1) * 256;
        vreg[p] = *(const float4*)&src[(i4 >> 4) * 64 + (i4 & 15) * 4];
    }

    float accA[8][4], accW[8][4];
    #pragma unroll
    for (int dp = 0; dp < 8; dp++)
        #pragma unroll
        for (int e = 0; e < 4; e++) { accA[dp][e] = 0.f; accW[dp][e] = 0.f; }
    float sw0 = 0.f, sw1 = 0.f;

    int srcA = (lane & ~3) | (c >> 1);
    int srcB = srcA + 2;
    bool odd = c & 1;

    for (int t = 0; t < 64; t++) {
        uint32_t bb = TB + (t & 1) * 6144;
        #pragma unroll
        for (int p = 0; p < 6; p++) {
            int arr = p >> 1;
            int i4 = tid + (p & 1) * 256;
            int key = i4 >> 4, blk = i4 & 15;
            *(float4*)&smu[bb + arr * 2048 + key * 64 + ((blk ^ (key & 7)) << 2)] = vreg[p];
        }
        __syncthreads();
        if (t < 63) {
            #pragma unroll
            for (int p = 0; p < 6; p++) {
                const float* src = (p < 2) ? Kb : (p < 4) ? Vcb : Vfb;
                int i4 = tid + (p & 1) * 256;
                vreg[p] = *(const float4*)&src[(t + 1) * 2048 + (i4 >> 4) * 64 + (i4 & 15) * 4];
            }
        }

        // recompute S for this warp's 16 rows x 32 keys
        float S[4][4];
        #pragma unroll
        for (int j = 0; j < 4; j++) { S[j][0]=0.f; S[j][1]=0.f; S[j][2]=0.f; S[j][3]=0.f; }
        #pragma unroll
        for (int ks = 0; ks < 8; ks++) {
            uint4 a = *(const uint4*)&smu[QP + (w * 8 + ks) * 132 + lane * 4];
            #pragma unroll
            for (int j = 0; j < 4; j++) {
                uint32_t base = bb + (j * 8 + g) * 64 + c;
                uint32_t b0 = smu[base + (((ks * 2) ^ g) << 2)];
                uint32_t b1 = smu[base + (((ks * 2 + 1) ^ g) << 2)];
                mma_tf32(S[j], a.x, a.y, a.z, a.w, b0, b1);
            }
        }

        #pragma unroll
        for (int j = 0; j < 4; j++) {
            float a0 = __expf(S[j][0]) * iZ0, a1 = __expf(S[j][1]) * iZ0;
            float a2 = __expf(S[j][2]) * iZ1, a3 = __expf(S[j][3]) * iZ1;
            float w0 = __expf(-a0), w1 = __expf(-a1), w2 = __expf(-a2), w3 = __expf(-a3);
            sw0 += w0 + w1; sw1 += w2 + w3;
            // transpose C-frag -> A-frag
            float pa0 = __shfl_sync(~0u, a0, srcA), pa1 = __shfl_sync(~0u, a1, srcA);
            float pa2 = __shfl_sync(~0u, a2, srcA), pa3 = __shfl_sync(~0u, a3, srcA);
            float qa0 = __shfl_sync(~0u, a0, srcB), qa1 = __shfl_sync(~0u, a1, srcB);
            float qa2 = __shfl_sync(~0u, a2, srcB), qa3 = __shfl_sync(~0u, a3, srcB);
            uint32_t A0 = f2tf(odd ? pa1 : pa0);
            uint32_t A1 = f2tf(odd ? pa3 : pa2);
            uint32_t A2 = f2tf(odd ? qa1 : qa0);
            uint32_t A3 = f2tf(odd ? qa3 : qa2);
            float pw0 = __shfl_sync(~0u, w0, srcA), pw1 = __shfl_sync(~0u, w1, srcA);
            float pw2 = __shfl_sync(~0u, w2, srcA), pw3 = __shfl_sync(~0u, w3, srcA);
            float qw0 = __shfl_sync(~0u, w0, srcB), qw1 = __shfl_sync(~0u, w1, srcB);
            float qw2 = __shfl_sync(~0u, w2, srcB), qw3 = __shfl_sync(~0u, w3, srcB);
            uint32_t W0 = f2tf(odd ? pw1 : pw0);
            uint32_t W1 = f2tf(odd ? pw3 : pw2);
            uint32_t W2 = f2tf(odd ? qw1 : qw0);
            uint32_t W3 = f2tf(odd ? qw3 : qw2);

            int rowc = j * 8 + c;
            #pragma unroll
            for (int dp = 0; dp < 8; dp++) {
                int dcol = dp * 8 + g;
                int blk = dcol >> 2;
                uint32_t o0 = rowc * 64 + ((blk ^ c) << 2) + (dcol & 3);
                uint32_t o1 = (rowc + 4) * 64 + ((blk ^ (c + 4)) << 2) + (dcol & 3);
                uint32_t bc0 = smu[bb + 2048 + o0];
                uint32_t bc1 = smu[bb + 2048 + o1];
                uint32_t bf0 = smu[bb + 4096 + o0];
                uint32_t bf1 = smu[bb + 4096 + o1];
                mma_tf32(accA[dp], A0, A1, A2, A3, bc0, bc1);
                mma_tf32(accW[dp], W0, W1, W2, W3, bf0, bf1);
            }
        }
    }

    sw0 += __shfl_xor_sync(~0u, sw0, 1);
    sw0 += __shfl_xor_sync(~0u, sw0, 2);
    sw1 += __shfl_xor_sync(~0u, sw1, 1);
    sw1 += __shfl_xor_sync(~0u, sw1, 2);
    float iw0 = (1.f - spv) / sw0, iw1 = (1.f - spv) / sw1;

    int r0 = qt * 128 + w * 16 + g;
    #pragma unroll
    for (int dp = 0; dp < 8; dp++) {
        int col = h * 64 + dp * 8 + 2 * c;
        *(float2*)&ob[(n * T_ + r0) * D_ + col] =
            make_float2(spv * accA[dp][0] + iw0 * accW[dp][0],
                        spv * accA[dp][1] + iw0 * accW[dp][1]);
        *(float2*)&ob[(n * T_ + r0 + 8) * D_ + col] =
            make_float2(spv * accA[dp][2] + iw1 * accW[dp][2],
                        spv * accA[dp][3] + iw1 * accW[dp][3]);
    }
}

// ---------------------------------------------------------------------------
extern "C" void kernel_launch(void* const* d_in, const int* in_sizes, int n_in,
                              void* d_out, int out_size) {
    const float* x   = (const float*)d_in[0];
    const float* y   = (const float*)d_in[1];
    const float* iw  = (const float*)d_in[2];
    const float* lw  = (const float*)d_in[3];
    const float* isc = (const float*)d_in[4];
    const float* lsc = (const float*)d_in[5];
    const float* sp  = (const float*)d_in[6];
    float* out = (float*)d_out;

    const int ATTN_SMEM = SMEM_WORDS * 4;   // 82944 bytes
    cudaFuncSetAttribute(attn_kernel, cudaFuncAttributeMaxDynamicSharedMemorySize, ATTN_SMEM);

    scale_kernel<<<1, 32>>>(isc, lsc);

    dim3 gq(1536 / 64, 4096 / 128);
    qkv_tf32_kernel<<<gq, 256>>>(x, iw, 0);
    qkv_tf32_kernel<<<gq, 256>>>(y, lw, 1);

    dim3 g2(T_ / 128, H_, 4);
    attn_kernel<<<g2, 256, ATTN_SMEM>>>(sp, out);
}

// round 10
// speedup vs baseline: 1.2626x; 1.0863x over previous
#include <cuda_runtime.h>
#include <cstdint>

#define N_  2
#define T_  2048
#define D_  512
#define H_  8
#define HD_ 64
#define NTD (N_*T_*D_)
#define NHTHD (N_*H_*T_*HD_)

// Scratch: [stream][q/k/v][n,h,t,hd], values pre-rounded to tf32 (rna)
__device__ float g_buf[2][3][NHTHD];
__device__ float g_sc[2][H_*HD_];
// p scratch: [blk(512)][warp(8)][t(64)][j(4)*32+lane] float4 (A-frag layout)
__device__ float4 g_p[512u*8u*64u*128u];

// attn smem word offsets
#define QP 0                    // Q A-frags: 64 groups * 132 = 8448 words
#define TB 8448                 // tile double-buffer
                                // pass1: K tile, 2048 words per buf
                                // pass2: Vc @+0, Vf @+2048 (4096 words per buf)
#define TBSTRIDE 4096
#define SMEM_WORDS (8448 + 2*4096)   // 16640 words = 66560 B

// ---------------------------------------------------------------------------
__global__ void scale_kernel(const float* __restrict__ isc,
                             const float* __restrict__ lsc) {
    int i = threadIdx.x;
    if (i >= 16) return;
    int s = i >> 3, h = i & 7;
    const float* src = (s == 0 ? isc : lsc) + h * HD_;
    float m = -1e30f;
    for (int d = 0; d < HD_; d++) m = fmaxf(m, src[d]);
    float Z = 0.f;
    for (int d = 0; d < HD_; d++) Z += __expf(src[d] - m);
    float inv = 1.f / Z;
    for (int d = 0; d < HD_; d++) g_sc[s][h*HD_ + d] = __expf(src[d] - m) * inv;
}

__device__ __forceinline__ uint32_t f2tf(float x) {
    uint32_t r;
    asm("cvt.rna.tf32.f32 %0, %1;" : "=r"(r) : "f"(x));
    return r;
}
__device__ __forceinline__ float tf32r(float x) { return __uint_as_float(f2tf(x)); }

__device__ __forceinline__ void mma_tf32(float (&d)[4],
                                         uint32_t a0, uint32_t a1, uint32_t a2, uint32_t a3,
                                         uint32_t b0, uint32_t b1) {
    asm volatile(
        "mma.sync.aligned.m16n8k8.row.col.f32.tf32.tf32.f32 "
        "{%0,%1,%2,%3}, {%4,%5,%6,%7}, {%8,%9}, {%0,%1,%2,%3};"
        : "+f"(d[0]), "+f"(d[1]), "+f"(d[2]), "+f"(d[3])
        : "r"(a0), "r"(a1), "r"(a2), "r"(a3), "r"(b0), "r"(b1));
}

// ---------------------------------------------------------------------------
// QKV projection, tf32 mma, 128(M) x 64(N) tiles, K=512, reg-prefetched.
// Writes tf32-rounded fp32 to plain [n,h,t,hd] layout. (Unchanged from R9.)
// ---------------------------------------------------------------------------
__global__ __launch_bounds__(256, 2)
void qkv_tf32_kernel(const float* __restrict__ z, const float* __restrict__ W, int stream) {
    __shared__ uint32_t ap[4224];
    __shared__ uint32_t bp[2112];
    int tid = threadIdx.x;
    int w = tid >> 5, lane = tid & 31;
    int g = lane >> 2, c = lane & 3;
    int rq = w & 3, nh = w >> 2;
    int c0 = blockIdx.x * 64;
    int m0 = blockIdx.y * 128;

    float acc[2][4][4];
    #pragma unroll
    for (int a = 0; a < 2; a++)
        #pragma unroll
        for (int b = 0; b < 4; b++)
            #pragma unroll
            for (int e = 0; e < 4; e++) acc[a][b][e] = 0.f;

    float4 zr[4], wr[2];
    #pragma unroll
    for (int p = 0; p < 4; p++) {
        int i4 = tid + p * 256;
        zr[p] = *(const float4*)&z[(m0 + (i4 >> 3)) * 512 + (i4 & 7) * 4];
    }
    #pragma unroll
    for (int p = 0; p < 2; p++) {
        int i4 = tid + p * 256;
        wr[p] = *(const float4*)&W[(c0 + (i4 >> 3)) * 512 + (i4 & 7) * 4];
    }

    for (int it = 0; it < 16; it++) {
        __syncthreads();
        #pragma unroll
        for (int p = 0; p < 4; p++) {
            int i4 = tid + p * 256;
            int row = i4 >> 3, kq = i4 & 7;
            int base = ((row >> 4) * 4 + (kq >> 1)) * 132 + (row & 7) * 16
                     + (kq & 1) * 2 + ((row >> 3) & 1);
            ap[base + 0]  = f2tf(zr[p].x);
            ap[base + 4]  = f2tf(zr[p].y);
            ap[base + 8]  = f2tf(zr[p].z);
            ap[base + 12] = f2tf(zr[p].w);
        }
        #pragma unroll
        for (int p = 0; p < 2; p++) {
            int i4 = tid + p * 256;
            int col = i4 >> 3, kq = i4 & 7;
            int base = ((col >> 3) * 4 + (kq >> 1)) * 66 + (col & 7) * 8 + (kq & 1);
            bp[base + 0] = f2tf(wr[p].x);
            bp[base + 2] = f2tf(wr[p].y);
            bp[base + 4] = f2tf(wr[p].z);
            bp[base + 6] = f2tf(wr[p].w);
        }
        __syncthreads();
        if (it < 15) {
            int k0 = (it + 1) * 32;
            #pragma unroll
            for (int p = 0; p < 4; p++) {
                int i4 = tid + p * 256;
                zr[p] = *(const float4*)&z[(m0 + (i4 >> 3)) * 512 + k0 + (i4 & 7) * 4];
            }
            #pragma unroll
            for (int p = 0; p < 2; p++) {
                int i4 = tid + p * 256;
                wr[p] = *(const float4*)&W[(c0 + (i4 >> 3)) * 512 + k0 + (i4 & 7) * 4];
            }
        }
        #pragma unroll
        for (int ks = 0; ks < 4; ks++) {
            uint4 a0 = *(const uint4*)&ap[((rq * 2 + 0) * 4 + ks) * 132 + lane * 4];
            uint4 a1 = *(const uint4*)&ap[((rq * 2 + 1) * 4 + ks) * 132 + lane * 4];
            #pragma unroll
            for (int np = 0; np < 4; np++) {
                uint2 b = *(const uint2*)&bp[((nh * 4 + np) * 4 + ks) * 66 + lane * 2];
                mma_tf32(acc[0][np], a0.x, a0.y, a0.z, a0.w, b.x, b.y);
                mma_tf32(acc[1][np], a1.x, a1.y, a1.z, a1.w, b.x, b.y);
            }
        }
    }

    int three = c0 >> 9;
    int h = (c0 >> 6) & 7;
    float* dst = g_buf[stream][three];
    #pragma unroll
    for (int grp = 0; grp < 2; grp++) {
        #pragma unroll
        for (int np = 0; np < 4; np++) {
            int colb = nh * 32 + np * 8 + 2 * c;
            float sx = 1.f, sy = 1.f;
            if (three == 0) {
                float2 s2 = *(const float2*)&g_sc[stream][h * 64 + colb];
                sx = s2.x; sy = s2.y;
            }
            int m = m0 + rq * 32 + grp * 16 + g;
            int nn = m >> 11, t = m & 2047;
            *(float2*)&dst[((nn * 8 + h) * 2048 + t) * 64 + colb] =
                make_float2(tf32r(acc[grp][np][0] * sx), tf32r(acc[grp][np][1] * sy));
            int m2 = m + 8;
            int nn2 = m2 >> 11, t2 = m2 & 2047;
            *(float2*)&dst[((nn2 * 8 + h) * 2048 + t2) * 64 + colb] =
                make_float2(tf32r(acc[grp][np][2] * sx), tf32r(acc[grp][np][3] * sy));
        }
    }
}

// ---------------------------------------------------------------------------
// Dual attention. Block = (stream, n, h, 128-row q-tile), 8 warps x 16 rows.
// No-max softmax (|S| <= ~1).
// Pass 1: QK^T (K staged via LDG->STS double-buffer), Z = sum exp(S),
//         p = exp(S) shuffled to A-frag layout and stored coalesced to gmem.
// Pass 2: p reloaded (coalesced LDG.128, MLP=8), a = p*iZ, w = exp(-a),
//         two AV mmas vs Vc/Vf staged in swizzled smem. No QK recompute.
// anti = softmax(max(attn)-attn) == softmax(-attn)
// ---------------------------------------------------------------------------
__global__ __launch_bounds__(256, 2)
void attn_kernel(const float* __restrict__ sp, float* __restrict__ out) {
    extern __shared__ uint32_t smu[];
    int tid = threadIdx.x;
    int w = tid >> 5, lane = tid & 31;
    int g = lane >> 2, c = lane & 3;
    int qt = blockIdx.x, h = blockIdx.y, zb = blockIdx.z;
    int s = zb >> 1, n = zb & 1;
    int blk = (zb * 8 + h) * 16 + qt;

    const float* Qb  = g_buf[s][0]     + ((n * H_ + h) * T_ + qt * 128) * HD_;
    const float* Kb  = g_buf[1 - s][1] + ((n * H_ + h) * T_) * HD_;
    const float* Vcb = g_buf[1 - s][2] + ((n * H_ + h) * T_) * HD_;
    const float* Vfb = g_buf[s][2]     + ((n * H_ + h) * T_) * HD_;
    float* ob = out + s * NTD;
    float spv = *sp;

    // stage Q [128x64] into A-frag layout once (values pre-rounded)
    #pragma unroll
    for (int p = 0; p < 8; p++) {
        int i4 = tid + p * 256;
        int row = i4 >> 4, kq = i4 & 15;
        float4 qv = *(const float4*)&Qb[row * 64 + kq * 4];
        int base = QP + ((row >> 4) * 8 + (kq >> 1)) * 132 + (row & 7) * 16
                 + (kq & 1) * 2 + ((row >> 3) & 1);
        smu[base + 0]  = __float_as_uint(qv.x);
        smu[base + 4]  = __float_as_uint(qv.y);
        smu[base + 8]  = __float_as_uint(qv.z);
        smu[base + 12] = __float_as_uint(qv.w);
    }

    int srcA = (lane & ~3) | (c >> 1);
    int srcB = srcA + 2;
    bool odd = lane & 1;

    // ================= pass 1: Z = sum exp(S), p -> gmem ====================
    float4 kreg[2];
    #pragma unroll
    for (int p = 0; p < 2; p++) {
        int i4 = tid + p * 256;
        kreg[p] = *(const float4*)&Kb[(i4 >> 4) * 64 + (i4 & 15) * 4];
    }

    float zs0 = 0.f, zs1 = 0.f;
    for (int t = 0; t < 64; t++) {
        uint32_t kb = TB + (t & 1) * TBSTRIDE;
        #pragma unroll
        for (int p = 0; p < 2; p++) {
            int i4 = tid + p * 256;
            int key = i4 >> 4, bk = i4 & 15;
            *(float4*)&smu[kb + key * 64 + ((bk ^ (key & 7)) << 2)] = kreg[p];
        }
        __syncthreads();
        if (t < 63) {
            #pragma unroll
            for (int p = 0; p < 2; p++) {
                int i4 = tid + p * 256;
                kreg[p] = *(const float4*)&Kb[(t + 1) * 2048 + (i4 >> 4) * 64 + (i4 & 15) * 4];
            }
        }
        float S[4][4];
        #pragma unroll
        for (int j = 0; j < 4; j++) { S[j][0]=0.f; S[j][1]=0.f; S[j][2]=0.f; S[j][3]=0.f; }
        #pragma unroll
        for (int ks = 0; ks < 8; ks++) {
            uint4 a = *(const uint4*)&smu[QP + (w * 8 + ks) * 132 + lane * 4];
            #pragma unroll
            for (int j = 0; j < 4; j++) {
                uint32_t base = kb + (j * 8 + g) * 64 + c;
                uint32_t b0 = smu[base + (((ks * 2) ^ g) << 2)];
                uint32_t b1 = smu[base + (((ks * 2 + 1) ^ g) << 2)];
                mma_tf32(S[j], a.x, a.y, a.z, a.w, b0, b1);
            }
        }
        // p = exp(S); Z accumulation; shuffle C-frag -> A-frag; coalesced STG
        float4* pg = &g_p[((blk * 8 + w) * 64 + t) * 128 + lane];
        #pragma unroll
        for (int j = 0; j < 4; j++) {
            float p0 = __expf(S[j][0]);
            float p1 = __expf(S[j][1]);
            float p2 = __expf(S[j][2]);
            float p3 = __expf(S[j][3]);
            zs0 += p0 + p1;
            zs1 += p2 + p3;
            float x0 = __shfl_sync(~0u, p0, srcA);
            float x1 = __shfl_sync(~0u, p1, srcA);
            float y0 = __shfl_sync(~0u, p2, srcA);
            float y1 = __shfl_sync(~0u, p3, srcA);
            float u0 = __shfl_sync(~0u, p0, srcB);
            float u1 = __shfl_sync(~0u, p1, srcB);
            float v0 = __shfl_sync(~0u, p2, srcB);
            float v1 = __shfl_sync(~0u, p3, srcB);
            float4 o;
            o.x = odd ? x1 : x0;   // a0: row g,   key c
            o.y = odd ? y1 : y0;   // a1: row g+8, key c
            o.z = odd ? u1 : u0;   // a2: row g,   key c+4
            o.w = odd ? v1 : v0;   // a3: row g+8, key c+4
            pg[j * 32] = o;
        }
    }
    zs0 += __shfl_xor_sync(~0u, zs0, 1);
    zs0 += __shfl_xor_sync(~0u, zs0, 2);
    zs1 += __shfl_xor_sync(~0u, zs1, 1);
    zs1 += __shfl_xor_sync(~0u, zs1, 2);
    float iZ0 = 1.f / zs0, iZ1 = 1.f / zs1;
    __syncthreads();   // pass-1 buffers done before pass-2 restaging

    // ======================= pass 2: attn/anti AV ===========================
    float4 vreg[4];
    #pragma unroll
    for (int p = 0; p < 4; p++) {
        const float* src = (p < 2) ? Vcb : Vfb;
        int i4 = tid + (p & 1) * 256;
        vreg[p] = *(const float4*)&src[(i4 >> 4) * 64 + (i4 & 15) * 4];
    }

    float accA[8][4], accW[8][4];
    #pragma unroll
    for (int dp = 0; dp < 8; dp++)
        #pragma unroll
        for (int e = 0; e < 4; e++) { accA[dp][e] = 0.f; accW[dp][e] = 0.f; }
    float sw0 = 0.f, sw1 = 0.f;

    for (int t = 0; t < 64; t++) {
        uint32_t bb = TB + (t & 1) * TBSTRIDE;
        #pragma unroll
        for (int p = 0; p < 4; p++) {
            int arr = p >> 1;
            int i4 = tid + (p & 1) * 256;
            int key = i4 >> 4, bk = i4 & 15;
            *(float4*)&smu[bb + arr * 2048 + key * 64 + ((bk ^ (key & 7)) << 2)] = vreg[p];
        }
        __syncthreads();
        if (t < 63) {
            #pragma unroll
            for (int p = 0; p < 4; p++) {
                const float* src = (p < 2) ? Vcb : Vfb;
                int i4 = tid + (p & 1) * 256;
                vreg[p] = *(const float4*)&src[(t + 1) * 2048 + (i4 >> 4) * 64 + (i4 & 15) * 4];
            }
        }

        // load p (A-frag layout, coalesced, 4 independent LDG.128)
        const float4* pg = &g_p[((blk * 8 + w) * 64 + t) * 128 + lane];
        float4 p4[4];
        #pragma unroll
        for (int j = 0; j < 4; j++) p4[j] = pg[j * 32];

        #pragma unroll
        for (int j = 0; j < 4; j++) {
            float a0 = p4[j].x * iZ0, a1 = p4[j].y * iZ1;
            float a2 = p4[j].z * iZ0, a3 = p4[j].w * iZ1;
            float w0 = __expf(-a0), w1 = __expf(-a1), w2 = __expf(-a2), w3 = __expf(-a3);
            sw0 += w0 + w2; sw1 += w1 + w3;
            uint32_t A0 = f2tf(a0), A1 = f2tf(a1), A2 = f2tf(a2), A3 = f2tf(a3);
            uint32_t W0 = f2tf(w0), W1 = f2tf(w1), W2 = f2tf(w2), W3 = f2tf(w3);
            int rowc = j * 8 + c;
            #pragma unroll
            for (int dp = 0; dp < 8; dp++) {
                int dcol = dp * 8 + g;
                int bk = dcol >> 2;
                uint32_t o0 = rowc * 64 + ((bk ^ c) << 2) + (dcol & 3);
                uint32_t o1 = (rowc + 4) * 64 + ((bk ^ (c + 4)) << 2) + (dcol & 3);
                uint32_t bc0 = smu[bb + o0];
                uint32_t bc1 = smu[bb + o1];
                uint32_t bf0 = smu[bb + 2048 + o0];
                uint32_t bf1 = smu[bb + 2048 + o1];
                mma_tf32(accA[dp], A0, A1, A2, A3, bc0, bc1);
                mma_tf32(accW[dp], W0, W1, W2, W3, bf0, bf1);
            }
        }
    }

    // anti row sums (reduce over quad lanes; rows are quad-private)
    sw0 += __shfl_xor_sync(~0u, sw0, 1);
    sw0 += __shfl_xor_sync(~0u, sw0, 2);
    sw1 += __shfl_xor_sync(~0u, sw1, 1);
    sw1 += __shfl_xor_sync(~0u, sw1, 2);
    float iw0 = (1.f - spv) / sw0, iw1 = (1.f - spv) / sw1;

    int r0 = qt * 128 + w * 16 + g;
    #pragma unroll
    for (int dp = 0; dp < 8; dp++) {
        int col = h * 64 + dp * 8 + 2 * c;
        *(float2*)&ob[(n * T_ + r0) * D_ + col] =
            make_float2(spv * accA[dp][0] + iw0 * accW[dp][0],
                        spv * accA[dp][1] + iw0 * accW[dp][1]);
        *(float2*)&ob[(n * T_ + r0 + 8) * D_ + col] =
            make_float2(spv * accA[dp][2] + iw1 * accW[dp][2],
                        spv * accA[dp][3] + iw1 * accW[dp][3]);
    }
}

// ---------------------------------------------------------------------------
extern "C" void kernel_launch(void* const* d_in, const int* in_sizes, int n_in,
                              void* d_out, int out_size) {
    const float* x   = (const float*)d_in[0];
    const float* y   = (const float*)d_in[1];
    const float* iw  = (const float*)d_in[2];
    const float* lw  = (const float*)d_in[3];
    const float* isc = (const float*)d_in[4];
    const float* lsc = (const float*)d_in[5];
    const float* sp  = (const float*)d_in[6];
    float* out = (float*)d_out;

    const int ATTN_SMEM = SMEM_WORDS * 4;   // 66560 bytes
    cudaFuncSetAttribute(attn_kernel, cudaFuncAttributeMaxDynamicSharedMemorySize, ATTN_SMEM);

    scale_kernel<<<1, 32>>>(isc, lsc);

    dim3 gq(1536 / 64, 4096 / 128);
    qkv_tf32_kernel<<<gq, 256>>>(x, iw, 0);
    qkv_tf32_kernel<<<gq, 256>>>(y, lw, 1);

    dim3 g2(T_ / 128, H_, 4);
    attn_kernel<<<g2, 256, ATTN_SMEM>>>(sp, out);
}

// round 11
// speedup vs baseline: 1.2720x; 1.0074x over previous
#include <cuda_runtime.h>
#include <cstdint>

#define N_  2
#define T_  2048
#define D_  512
#define H_  8
#define HD_ 64
#define NTD (N_*T_*D_)
#define NHTHD (N_*H_*T_*HD_)

// Scratch: [stream][q/k/v][n,h,t,hd], values pre-rounded to tf32 (rna)
__device__ float g_buf[2][3][NHTHD];
__device__ float g_sc[2][H_*HD_];
// p scratch: [blk(512)][warp(8)][t(64)][j(4)*32+lane] float4 (A-frag layout)
__device__ float4 g_p[512u*8u*64u*128u];

// attn smem word offsets
#define QP 0                    // Q A-frags: 64 groups * 132 = 8448 words (izt reuses words 0..127 after pass 1)
#define TB 8448                 // tile double-buffer
#define TBSTRIDE 4096
#define SMEM_WORDS (8448 + 2*4096)   // 16640 words = 66560 B

// ---------------------------------------------------------------------------
__global__ void scale_kernel(const float* __restrict__ isc,
                             const float* __restrict__ lsc) {
    int i = threadIdx.x;
    if (i >= 16) return;
    int s = i >> 3, h = i & 7;
    const float* src = (s == 0 ? isc : lsc) + h * HD_;
    float m = -1e30f;
    for (int d = 0; d < HD_; d++) m = fmaxf(m, src[d]);
    float Z = 0.f;
    for (int d = 0; d < HD_; d++) Z += __expf(src[d] - m);
    float inv = 1.f / Z;
    for (int d = 0; d < HD_; d++) g_sc[s][h*HD_ + d] = __expf(src[d] - m) * inv;
}

__device__ __forceinline__ uint32_t f2tf(float x) {
    uint32_t r;
    asm("cvt.rna.tf32.f32 %0, %1;" : "=r"(r) : "f"(x));
    return r;
}
__device__ __forceinline__ float tf32r(float x) { return __uint_as_float(f2tf(x)); }

__device__ __forceinline__ void mma_tf32(float (&d)[4],
                                         uint32_t a0, uint32_t a1, uint32_t a2, uint32_t a3,
                                         uint32_t b0, uint32_t b1) {
    asm volatile(
        "mma.sync.aligned.m16n8k8.row.col.f32.tf32.tf32.f32 "
        "{%0,%1,%2,%3}, {%4,%5,%6,%7}, {%8,%9}, {%0,%1,%2,%3};"
        : "+f"(d[0]), "+f"(d[1]), "+f"(d[2]), "+f"(d[3])
        : "r"(a0), "r"(a1), "r"(a2), "r"(a3), "r"(b0), "r"(b1));
}

// ---------------------------------------------------------------------------
// QKV projection, tf32 mma, 128(M) x 64(N) tiles, K=512, reg-prefetched.
// Writes tf32-rounded fp32 to plain [n,h,t,hd] layout. (Unchanged from R10.)
// ---------------------------------------------------------------------------
__global__ __launch_bounds__(256, 2)
void qkv_tf32_kernel(const float* __restrict__ z, const float* __restrict__ W, int stream) {
    __shared__ uint32_t ap[4224];
    __shared__ uint32_t bp[2112];
    int tid = threadIdx.x;
    int w = tid >> 5, lane = tid & 31;
    int g = lane >> 2, c = lane & 3;
    int rq = w & 3, nh = w >> 2;
    int c0 = blockIdx.x * 64;
    int m0 = blockIdx.y * 128;

    float acc[2][4][4];
    #pragma unroll
    for (int a = 0; a < 2; a++)
        #pragma unroll
        for (int b = 0; b < 4; b++)
            #pragma unroll
            for (int e = 0; e < 4; e++) acc[a][b][e] = 0.f;

    float4 zr[4], wr[2];
    #pragma unroll
    for (int p = 0; p < 4; p++) {
        int i4 = tid + p * 256;
        zr[p] = *(const float4*)&z[(m0 + (i4 >> 3)) * 512 + (i4 & 7) * 4];
    }
    #pragma unroll
    for (int p = 0; p < 2; p++) {
        int i4 = tid + p * 256;
        wr[p] = *(const float4*)&W[(c0 + (i4 >> 3)) * 512 + (i4 & 7) * 4];
    }

    for (int it = 0; it < 16; it++) {
        __syncthreads();
        #pragma unroll
        for (int p = 0; p < 4; p++) {
            int i4 = tid + p * 256;
            int row = i4 >> 3, kq = i4 & 7;
            int base = ((row >> 4) * 4 + (kq >> 1)) * 132 + (row & 7) * 16
                     + (kq & 1) * 2 + ((row >> 3) & 1);
            ap[base + 0]  = f2tf(zr[p].x);
            ap[base + 4]  = f2tf(zr[p].y);
            ap[base + 8]  = f2tf(zr[p].z);
            ap[base + 12] = f2tf(zr[p].w);
        }
        #pragma unroll
        for (int p = 0; p < 2; p++) {
            int i4 = tid + p * 256;
            int col = i4 >> 3, kq = i4 & 7;
            int base = ((col >> 3) * 4 + (kq >> 1)) * 66 + (col & 7) * 8 + (kq & 1);
            bp[base + 0] = f2tf(wr[p].x);
            bp[base + 2] = f2tf(wr[p].y);
            bp[base + 4] = f2tf(wr[p].z);
            bp[base + 6] = f2tf(wr[p].w);
        }
        __syncthreads();
        if (it < 15) {
            int k0 = (it + 1) * 32;
            #pragma unroll
            for (int p = 0; p < 4; p++) {
                int i4 = tid + p * 256;
                zr[p] = *(const float4*)&z[(m0 + (i4 >> 3)) * 512 + k0 + (i4 & 7) * 4];
            }
            #pragma unroll
            for (int p = 0; p < 2; p++) {
                int i4 = tid + p * 256;
                wr[p] = *(const float4*)&W[(c0 + (i4 >> 3)) * 512 + k0 + (i4 & 7) * 4];
            }
        }
        #pragma unroll
        for (int ks = 0; ks < 4; ks++) {
            uint4 a0 = *(const uint4*)&ap[((rq * 2 + 0) * 4 + ks) * 132 + lane * 4];
            uint4 a1 = *(const uint4*)&ap[((rq * 2 + 1) * 4 + ks) * 132 + lane * 4];
            #pragma unroll
            for (int np = 0; np < 4; np++) {
                uint2 b = *(const uint2*)&bp[((nh * 4 + np) * 4 + ks) * 66 + lane * 2];
                mma_tf32(acc[0][np], a0.x, a0.y, a0.z, a0.w, b.x, b.y);
                mma_tf32(acc[1][np], a1.x, a1.y, a1.z, a1.w, b.x, b.y);
            }
        }
    }

    int three = c0 >> 9;
    int h = (c0 >> 6) & 7;
    float* dst = g_buf[stream][three];
    #pragma unroll
    for (int grp = 0; grp < 2; grp++) {
        #pragma unroll
        for (int np = 0; np < 4; np++) {
            int colb = nh * 32 + np * 8 + 2 * c;
            float sx = 1.f, sy = 1.f;
            if (three == 0) {
                float2 s2 = *(const float2*)&g_sc[stream][h * 64 + colb];
                sx = s2.x; sy = s2.y;
            }
            int m = m0 + rq * 32 + grp * 16 + g;
            int nn = m >> 11, t = m & 2047;
            *(float2*)&dst[((nn * 8 + h) * 2048 + t) * 64 + colb] =
                make_float2(tf32r(acc[grp][np][0] * sx), tf32r(acc[grp][np][1] * sy));
            int m2 = m + 8;
            int nn2 = m2 >> 11, t2 = m2 & 2047;
            *(float2*)&dst[((nn2 * 8 + h) * 2048 + t2) * 64 + colb] =
                make_float2(tf32r(acc[grp][np][2] * sx), tf32r(acc[grp][np][3] * sy));
        }
    }
}

// ---------------------------------------------------------------------------
// Dual attention. Block = (stream, n, h, 128-row q-tile), 8 warps.
// No-max softmax (|S| <= ~1).
// Pass 1 (16 rows/warp, Q frags in REGISTERS): QK^T, Z = sum exp(S),
//         p = exp(S) shuffled to A-frag layout, coalesced STG to g_p.
//         iZ published to smem table.
// Pass 2 (32 rows x 32 dcols/warp): a = p*iZ, w = exp(-a); V B-frags
//         hoisted across the two row-groups (halves B LDS traffic).
// anti = softmax(max(attn)-attn) == softmax(-attn)
// ---------------------------------------------------------------------------
__global__ __launch_bounds__(256, 2)
void attn_kernel(const float* __restrict__ sp, float* __restrict__ out) {
    extern __shared__ uint32_t smu[];
    int tid = threadIdx.x;
    int w = tid >> 5, lane = tid & 31;
    int g = lane >> 2, c = lane & 3;
    int qt = blockIdx.x, h = blockIdx.y, zb = blockIdx.z;
    int s = zb >> 1, n = zb & 1;
    int blk = (zb * 8 + h) * 16 + qt;

    const float* Qb  = g_buf[s][0]     + ((n * H_ + h) * T_ + qt * 128) * HD_;
    const float* Kb  = g_buf[1 - s][1] + ((n * H_ + h) * T_) * HD_;
    const float* Vcb = g_buf[1 - s][2] + ((n * H_ + h) * T_) * HD_;
    const float* Vfb = g_buf[s][2]     + ((n * H_ + h) * T_) * HD_;
    float* ob = out + s * NTD;
    float spv = *sp;

    // stage Q [128x64] into A-frag layout once (values pre-rounded)
    #pragma unroll
    for (int p = 0; p < 8; p++) {
        int i4 = tid + p * 256;
        int row = i4 >> 4, kq = i4 & 15;
        float4 qv = *(const float4*)&Qb[row * 64 + kq * 4];
        int base = QP + ((row >> 4) * 8 + (kq >> 1)) * 132 + (row & 7) * 16
                 + (kq & 1) * 2 + ((row >> 3) & 1);
        smu[base + 0]  = __float_as_uint(qv.x);
        smu[base + 4]  = __float_as_uint(qv.y);
        smu[base + 8]  = __float_as_uint(qv.z);
        smu[base + 12] = __float_as_uint(qv.w);
    }
    __syncthreads();

    // pull this warp's Q A-frags into registers for the whole of pass 1
    uint4 qf[8];
    #pragma unroll
    for (int ks = 0; ks < 8; ks++)
        qf[ks] = *(const uint4*)&smu[QP + (w * 8 + ks) * 132 + lane * 4];

    int srcA = (lane & ~3) | (c >> 1);
    int srcB = srcA + 2;
    bool odd = lane & 1;

    // ================= pass 1: Z = sum exp(S), p -> gmem ====================
    float4 kreg[2];
    #pragma unroll
    for (int p = 0; p < 2; p++) {
        int i4 = tid + p * 256;
        kreg[p] = *(const float4*)&Kb[(i4 >> 4) * 64 + (i4 & 15) * 4];
    }

    float zs0 = 0.f, zs1 = 0.f;
    for (int t = 0; t < 64; t++) {
        uint32_t kb = TB + (t & 1) * TBSTRIDE;
        #pragma unroll
        for (int p = 0; p < 2; p++) {
            int i4 = tid + p * 256;
            int key = i4 >> 4, bk = i4 & 15;
            *(float4*)&smu[kb + key * 64 + ((bk ^ (key & 7)) << 2)] = kreg[p];
        }
        __syncthreads();
        if (t < 63) {
            #pragma unroll
            for (int p = 0; p < 2; p++) {
                int i4 = tid + p * 256;
                kreg[p] = *(const float4*)&Kb[(t + 1) * 2048 + (i4 >> 4) * 64 + (i4 & 15) * 4];
            }
        }
        float S[4][4];
        #pragma unroll
        for (int j = 0; j < 4; j++) { S[j][0]=0.f; S[j][1]=0.f; S[j][2]=0.f; S[j][3]=0.f; }
        #pragma unroll
        for (int ks = 0; ks < 8; ks++) {
            uint4 a = qf[ks];
            #pragma unroll
            for (int j = 0; j < 4; j++) {
                uint32_t base = kb + (j * 8 + g) * 64 + c;
                uint32_t b0 = smu[base + (((ks * 2) ^ g) << 2)];
                uint32_t b1 = smu[base + (((ks * 2 + 1) ^ g) << 2)];
                mma_tf32(S[j], a.x, a.y, a.z, a.w, b0, b1);
            }
        }
        // p = exp(S); Z accumulation; shuffle C-frag -> A-frag; coalesced STG
        float4* pg = &g_p[((blk * 8 + w) * 64 + t) * 128 + lane];
        #pragma unroll
        for (int j = 0; j < 4; j++) {
            float p0 = __expf(S[j][0]);
            float p1 = __expf(S[j][1]);
            float p2 = __expf(S[j][2]);
            float p3 = __expf(S[j][3]);
            zs0 += p0 + p1;
            zs1 += p2 + p3;
            float x0 = __shfl_sync(~0u, p0, srcA);
            float x1 = __shfl_sync(~0u, p1, srcA);
            float y0 = __shfl_sync(~0u, p2, srcA);
            float y1 = __shfl_sync(~0u, p3, srcA);
            float u0 = __shfl_sync(~0u, p0, srcB);
            float u1 = __shfl_sync(~0u, p1, srcB);
            float v0 = __shfl_sync(~0u, p2, srcB);
            float v1 = __shfl_sync(~0u, p3, srcB);
            float4 o;
            o.x = odd ? x1 : x0;   // a0: row g,   key c
            o.y = odd ? y1 : y0;   // a1: row g+8, key c
            o.z = odd ? u1 : u0;   // a2: row g,   key c+4
            o.w = odd ? v1 : v0;   // a3: row g+8, key c+4
            pg[j * 32] = o;
        }
    }
    zs0 += __shfl_xor_sync(~0u, zs0, 1);
    zs0 += __shfl_xor_sync(~0u, zs0, 2);
    zs1 += __shfl_xor_sync(~0u, zs1, 1);
    zs1 += __shfl_xor_sync(~0u, zs1, 2);

    // publish iZ per row (QP region is dead now; reuse words 0..127)
    float* izt = (float*)smu;
    if (c == 0) {
        izt[w * 16 + g]     = 1.f / zs0;
        izt[w * 16 + g + 8] = 1.f / zs1;
    }
    __syncthreads();

    // ======================= pass 2: attn/anti AV ===========================
    // warp = rows [rq*32, rq*32+32) x dcols [dh*32, dh*32+32)
    int rq = w & 3, dh = w >> 2;
    float iz0[2], iz1[2];
    #pragma unroll
    for (int grp = 0; grp < 2; grp++) {
        int rgi = rq * 2 + grp;
        iz0[grp] = izt[rgi * 16 + g];
        iz1[grp] = izt[rgi * 16 + g + 8];
    }

    float4 vreg[4];
    #pragma unroll
    for (int p = 0; p < 4; p++) {
        const float* src = (p < 2) ? Vcb : Vfb;
        int i4 = tid + (p & 1) * 256;
        vreg[p] = *(const float4*)&src[(i4 >> 4) * 64 + (i4 & 15) * 4];
    }

    float accA[2][4][4], accW[2][4][4];
    #pragma unroll
    for (int grp = 0; grp < 2; grp++)
        #pragma unroll
        for (int dp = 0; dp < 4; dp++)
            #pragma unroll
            for (int e = 0; e < 4; e++) { accA[grp][dp][e] = 0.f; accW[grp][dp][e] = 0.f; }
    float sw0[2] = {0.f, 0.f}, sw1[2] = {0.f, 0.f};

    for (int t = 0; t < 64; t++) {
        uint32_t bb = TB + (t & 1) * TBSTRIDE;
        #pragma unroll
        for (int p = 0; p < 4; p++) {
            int arr = p >> 1;
            int i4 = tid + (p & 1) * 256;
            int key = i4 >> 4, bk = i4 & 15;
            *(float4*)&smu[bb + arr * 2048 + key * 64 + ((bk ^ (key & 7)) << 2)] = vreg[p];
        }
        __syncthreads();
        if (t < 63) {
            #pragma unroll
            for (int p = 0; p < 4; p++) {
                const float* src = (p < 2) ? Vcb : Vfb;
                int i4 = tid + (p & 1) * 256;
                vreg[p] = *(const float4*)&src[(t + 1) * 2048 + (i4 >> 4) * 64 + (i4 & 15) * 4];
            }
        }

        // p for both row groups (8 independent coalesced LDG.128)
        float4 p4[2][4];
        #pragma unroll
        for (int grp = 0; grp < 2; grp++) {
            const float4* pg = &g_p[((blk * 8 + rq * 2 + grp) * 64 + t) * 128 + lane];
            #pragma unroll
            for (int j = 0; j < 4; j++) p4[grp][j] = pg[j * 32];
        }

        #pragma unroll
        for (int j = 0; j < 4; j++) {
            uint32_t Af[2][4], Wf[2][4];
            #pragma unroll
            for (int grp = 0; grp < 2; grp++) {
                float a0 = p4[grp][j].x * iz0[grp], a1 = p4[grp][j].y * iz1[grp];
                float a2 = p4[grp][j].z * iz0[grp], a3 = p4[grp][j].w * iz1[grp];
                float w0 = __expf(-a0), w1 = __expf(-a1), w2 = __expf(-a2), w3 = __expf(-a3);
                sw0[grp] += w0 + w2; sw1[grp] += w1 + w3;
                Af[grp][0] = f2tf(a0); Af[grp][1] = f2tf(a1);
                Af[grp][2] = f2tf(a2); Af[grp][3] = f2tf(a3);
                Wf[grp][0] = f2tf(w0); Wf[grp][1] = f2tf(w1);
                Wf[grp][2] = f2tf(w2); Wf[grp][3] = f2tf(w3);
            }
            int rowc = j * 8 + c;
            #pragma unroll
            for (int dp = 0; dp < 4; dp++) {
                int dcol = (dh * 4 + dp) * 8 + g;
                int bk = dcol >> 2;
                uint32_t o0 = rowc * 64 + ((bk ^ c) << 2) + (dcol & 3);
                uint32_t o1 = (rowc + 4) * 64 + ((bk ^ (c + 4)) << 2) + (dcol & 3);
                uint32_t bc0 = smu[bb + o0];
                uint32_t bc1 = smu[bb + o1];
                uint32_t bf0 = smu[bb + 2048 + o0];
                uint32_t bf1 = smu[bb + 2048 + o1];
                #pragma unroll
                for (int grp = 0; grp < 2; grp++) {
                    mma_tf32(accA[grp][dp], Af[grp][0], Af[grp][1], Af[grp][2], Af[grp][3], bc0, bc1);
                    mma_tf32(accW[grp][dp], Wf[grp][0], Wf[grp][1], Wf[grp][2], Wf[grp][3], bf0, bf1);
                }
            }
        }
    }

    // anti row sums are warp-complete (keys not split): quad-reduce + write out
    #pragma unroll
    for (int grp = 0; grp < 2; grp++) {
        float s0 = sw0[grp], s1 = sw1[grp];
        s0 += __shfl_xor_sync(~0u, s0, 1);
        s0 += __shfl_xor_sync(~0u, s0, 2);
        s1 += __shfl_xor_sync(~0u, s1, 1);
        s1 += __shfl_xor_sync(~0u, s1, 2);
        float iw0 = (1.f - spv) / s0, iw1 = (1.f - spv) / s1;
        int r = qt * 128 + rq * 32 + grp * 16 + g;
        #pragma unroll
        for (int dp = 0; dp < 4; dp++) {
            int col = h * 64 + (dh * 4 + dp) * 8 + 2 * c;
            *(float2*)&ob[(n * T_ + r) * D_ + col] =
                make_float2(spv * accA[grp][dp][0] + iw0 * accW[grp][dp][0],
                            spv * accA[grp][dp][1] + iw0 * accW[grp][dp][1]);
            *(float2*)&ob[(n * T_ + r + 8) * D_ + col] =
                make_float2(spv * accA[grp][dp][2] + iw1 * accW[grp][dp][2],
                            spv * accA[grp][dp][3] + iw1 * accW[grp][dp][3]);
        }
    }
}

// ---------------------------------------------------------------------------
extern "C" void kernel_launch(void* const* d_in, const int* in_sizes, int n_in,
                              void* d_out, int out_size) {
    const float* x   = (const float*)d_in[0];
    const float* y   = (const float*)d_in[1];
    const float* iw  = (const float*)d_in[2];
    const float* lw  = (const float*)d_in[3];
    const float* isc = (const float*)d_in[4];
    const float* lsc = (const float*)d_in[5];
    const float* sp  = (const float*)d_in[6];
    float* out = (float*)d_out;

    const int ATTN_SMEM = SMEM_WORDS * 4;   // 66560 bytes
    cudaFuncSetAttribute(attn_kernel, cudaFuncAttributeMaxDynamicSharedMemorySize, ATTN_SMEM);

    scale_kernel<<<1, 32>>>(isc, lsc);

    dim3 gq(1536 / 64, 4096 / 128);
    qkv_tf32_kernel<<<gq, 256>>>(x, iw, 0);
    qkv_tf32_kernel<<<gq, 256>>>(y, lw, 1);

    dim3 g2(T_ / 128, H_, 4);
    attn_kernel<<<g2, 256, ATTN_SMEM>>>(sp, out);
}